// round 5
// baseline (speedup 1.0000x reference)
#include <cuda_runtime.h>
#include <cuda_fp16.h>
#include <cstdint>

#define CHAR_VOCAB 1001
#define EMB 256
#define H 192
#define G3 576   // 3*H
#define BATCH 32
#define SEQL 2048
#define NSPAN 512

// ---------------- scratch (no cudaMalloc allowed) ----------------
__device__ float g_proj[2][CHAR_VOCAB * G3];                 // 2 x 2.3 MB
__device__ float g_allh[(size_t)BATCH * SEQL * 2 * H];       // 100.7 MB

// ---------------- kernel 1: proj tables ----------------
// proj[d][v][g] = dot(emb[v], w_ih_d[g]) + b_ih_d[g]
#define VB 16
__global__ void proj_kernel(const float* __restrict__ emb,
                            const float* __restrict__ w_ih_f, const float* __restrict__ b_ih_f,
                            const float* __restrict__ w_ih_b, const float* __restrict__ b_ih_b) {
    __shared__ float embs[VB][EMB];
    const int dir = blockIdx.y;
    const float* __restrict__ w  = dir ? w_ih_b : w_ih_f;
    const float* __restrict__ bi = dir ? b_ih_b : b_ih_f;
    const int v0 = blockIdx.x * VB;

    for (int i = threadIdx.x; i < VB * EMB; i += blockDim.x) {
        int v = v0 + i / EMB;
        embs[i / EMB][i % EMB] = (v < CHAR_VOCAB) ? emb[(size_t)v * EMB + (i % EMB)] : 0.f;
    }
    __syncthreads();

    const int g = threadIdx.x;  // 0..575
    float acc[VB];
#pragma unroll
    for (int i = 0; i < VB; i++) acc[i] = 0.f;

    const float4* __restrict__ w4 = (const float4*)(w + (size_t)g * EMB);
    for (int e4 = 0; e4 < EMB / 4; e4++) {
        float4 wv = w4[e4];
#pragma unroll
        for (int i = 0; i < VB; i++) {
            float4 ev = *(const float4*)&embs[i][e4 * 4];
            acc[i] = fmaf(wv.x, ev.x, fmaf(wv.y, ev.y, fmaf(wv.z, ev.z, fmaf(wv.w, ev.w, acc[i]))));
        }
    }
    float bb = bi[g];
#pragma unroll
    for (int i = 0; i < VB; i++) {
        int v = v0 + i;
        if (v < CHAR_VOCAB) g_proj[dir][(size_t)v * G3 + g] = acc[i] + bb;
    }
}

// ---------------- kernel 2: GRU recurrence ----------------
// grid (2 dirs, 32 batch), 192 threads. W_hh fp16 in smem, everything else fp32.
// smem: W 221184 B + ids 8192 B + 2x h buffers 1536 B = 230912 B
#define SMEM_W_BYTES   (3 * 24 * H * 8 * 2)   // 221184
#define SMEM_IDS_OFF   SMEM_W_BYTES
#define SMEM_H_OFF     (SMEM_W_BYTES + SEQL * 4)
#define SMEM_TOTAL     (SMEM_H_OFF + 2 * H * 4)

__device__ __forceinline__ float sigf(float x) {
    return __fdividef(1.f, 1.f + __expf(-x));
}
__device__ __forceinline__ float tanhf_fast(float x) {
    // tanh(x) = 2*sigmoid(2x) - 1  (exp-based, ~1e-7 accuracy)
    return fmaf(2.f, sigf(2.f * x), -1.f);
}

__global__ void __launch_bounds__(192, 1)
gru_kernel(const int* __restrict__ char_ids,
           const float* __restrict__ w_hh_f, const float* __restrict__ b_hh_f,
           const float* __restrict__ w_hh_b, const float* __restrict__ b_hh_b) {
    extern __shared__ unsigned char smem[];
    __half* Ws   = (__half*)smem;                     // [3][24][192][8] halves
    int*    ids_s = (int*)(smem + SMEM_IDS_OFF);      // [2048]
    float*  hA   = (float*)(smem + SMEM_H_OFF);       // [192]
    float*  hB   = hA + H;                            // [192]

    const int dir = blockIdx.x;
    const int b   = blockIdx.y;
    const float* __restrict__ whh = dir ? w_hh_b : w_hh_f;
    const float* __restrict__ bhh = dir ? b_hh_b : b_hh_f;
    const float* __restrict__ proj = g_proj[dir];
    const int tid = threadIdx.x;

    // Stage W_hh into smem as fp16, layout [gate][k/8][row%192][k%8] so that
    // LDS.128 per lane is contiguous across the warp (conflict-free).
    for (int idx = tid; idx < G3 * H; idx += blockDim.x) {
        int row = idx / H, k = idx % H;
        int gg = row / H, j = row % H;
        Ws[((((size_t)gg * 24) + (k >> 3)) * H + j) * 8 + (k & 7)] = __float2half_rn(whh[idx]);
    }
    const int* __restrict__ myids = char_ids + (size_t)b * SEQL;
    for (int t = tid; t < SEQL; t += blockDim.x) ids_s[t] = myids[t];
    hA[tid] = 0.f;
    hB[tid] = 0.f;
    __syncthreads();

    const int j = tid;
    const float bhr = bhh[j], bhz = bhh[H + j], bhn = bhh[2 * H + j];
    float h_j = 0.f;
    float* allh_base = g_allh + ((size_t)b * SEQL) * (2 * H) + dir * H + j;

    // prefetch xp for step 0
    {
        int t0 = dir ? (SEQL - 1) : 0;
        int id0 = ids_s[t0];
        (void)id0;
    }
    int id0 = ids_s[dir ? (SEQL - 1) : 0];
    const float* p0 = proj + (size_t)id0 * G3 + j;
    float xr = p0[0], xz = p0[H], xn = p0[2 * H];

    const uint4* __restrict__ W4 = (const uint4*)Ws;  // [3*24][192] of 8-half vectors

#pragma unroll 1
    for (int s = 0; s < SEQL; s++) {
        // prefetch next step's xp (independent of h -> fully hidden)
        int sn = (s + 1 < SEQL) ? s + 1 : s;
        int tn = dir ? (SEQL - 1 - sn) : sn;
        int idn = ids_s[tn];
        const float* pn = proj + (size_t)idn * G3 + j;
        float xrN = pn[0], xzN = pn[H], xnN = pn[2 * H];

        const float* hb = (s & 1) ? hB : hA;
        float aR0 = bhr, aR1 = 0.f;
        float aZ0 = bhz, aZ1 = 0.f;
        float aN0 = bhn, aN1 = 0.f;

#pragma unroll
        for (int kg = 0; kg < 24; kg++) {
            float4 h0 = *(const float4*)(hb + kg * 8);
            float4 h1 = *(const float4*)(hb + kg * 8 + 4);
            uint4 wr = W4[(0 * 24 + kg) * H + j];
            uint4 wz = W4[(1 * 24 + kg) * H + j];
            uint4 wn = W4[(2 * 24 + kg) * H + j];
            {
                float2 f0 = __half22float2(*(__half2*)&wr.x);
                float2 f1 = __half22float2(*(__half2*)&wr.y);
                float2 f2 = __half22float2(*(__half2*)&wr.z);
                float2 f3 = __half22float2(*(__half2*)&wr.w);
                aR0 = fmaf(f0.x, h0.x, aR0); aR1 = fmaf(f0.y, h0.y, aR1);
                aR0 = fmaf(f1.x, h0.z, aR0); aR1 = fmaf(f1.y, h0.w, aR1);
                aR0 = fmaf(f2.x, h1.x, aR0); aR1 = fmaf(f2.y, h1.y, aR1);
                aR0 = fmaf(f3.x, h1.z, aR0); aR1 = fmaf(f3.y, h1.w, aR1);
            }
            {
                float2 f0 = __half22float2(*(__half2*)&wz.x);
                float2 f1 = __half22float2(*(__half2*)&wz.y);
                float2 f2 = __half22float2(*(__half2*)&wz.z);
                float2 f3 = __half22float2(*(__half2*)&wz.w);
                aZ0 = fmaf(f0.x, h0.x, aZ0); aZ1 = fmaf(f0.y, h0.y, aZ1);
                aZ0 = fmaf(f1.x, h0.z, aZ0); aZ1 = fmaf(f1.y, h0.w, aZ1);
                aZ0 = fmaf(f2.x, h1.x, aZ0); aZ1 = fmaf(f2.y, h1.y, aZ1);
                aZ0 = fmaf(f3.x, h1.z, aZ0); aZ1 = fmaf(f3.y, h1.w, aZ1);
            }
            {
                float2 f0 = __half22float2(*(__half2*)&wn.x);
                float2 f1 = __half22float2(*(__half2*)&wn.y);
                float2 f2 = __half22float2(*(__half2*)&wn.z);
                float2 f3 = __half22float2(*(__half2*)&wn.w);
                aN0 = fmaf(f0.x, h0.x, aN0); aN1 = fmaf(f0.y, h0.y, aN1);
                aN0 = fmaf(f1.x, h0.z, aN0); aN1 = fmaf(f1.y, h0.w, aN1);
                aN0 = fmaf(f2.x, h1.x, aN0); aN1 = fmaf(f2.y, h1.y, aN1);
                aN0 = fmaf(f3.x, h1.z, aN0); aN1 = fmaf(f3.y, h1.w, aN1);
            }
        }

        float r = sigf(xr + aR0 + aR1);
        float z = sigf(xz + aZ0 + aZ1);
        float n = tanhf_fast(fmaf(r, aN0 + aN1, xn));
        h_j = fmaf(z, h_j - n, n);   // (1-z)*n + z*h

        float* ho = (s & 1) ? hA : hB;
        ho[j] = h_j;
        int t = dir ? (SEQL - 1 - s) : s;
        allh_base[(size_t)t * (2 * H)] = h_j;

        xr = xrN; xz = xzN; xn = xnN;
        __syncthreads();
    }
}

// ---------------- kernel 3: gather ----------------
// out[b][s][0:384]   = all_h[b][start_ids[b][s]][:]
// out[b][s][384:768] = all_h[b][end_ids[b][s]][:]
__global__ void gather_kernel(const int* __restrict__ start_ids,
                              const int* __restrict__ end_ids,
                              float* __restrict__ out) {
    const int s = blockIdx.x, b = blockIdx.y;
    const int tid = threadIdx.x;  // 192 threads, 1 float4 each
    const int st = start_ids[(size_t)b * NSPAN + s];
    const int en = end_ids[(size_t)b * NSPAN + s];
    float4* orow = (float4*)(out + ((size_t)b * NSPAN + s) * 768);
    const float4* allh = (const float4*)g_allh;
    if (tid < 96) {
        orow[tid] = allh[((size_t)b * SEQL + st) * 96 + tid];
    } else {
        orow[tid] = allh[((size_t)b * SEQL + en) * 96 + (tid - 96)];
    }
}

// ---------------- launch ----------------
extern "C" void kernel_launch(void* const* d_in, const int* in_sizes, int n_in,
                              void* d_out, int out_size) {
    const int*   char_ids  = (const int*)d_in[0];
    const int*   start_ids = (const int*)d_in[1];
    const int*   end_ids   = (const int*)d_in[2];
    const float* emb       = (const float*)d_in[3];
    const float* w_ih_f    = (const float*)d_in[4];
    const float* w_hh_f    = (const float*)d_in[5];
    const float* b_ih_f    = (const float*)d_in[6];
    const float* b_hh_f    = (const float*)d_in[7];
    const float* w_ih_b    = (const float*)d_in[8];
    const float* w_hh_b    = (const float*)d_in[9];
    const float* b_ih_b    = (const float*)d_in[10];
    const float* b_hh_b    = (const float*)d_in[11];
    float* out = (float*)d_out;

    cudaFuncSetAttribute(gru_kernel, cudaFuncAttributeMaxDynamicSharedMemorySize, SMEM_TOTAL);

    // 1) projection tables: proj[d] = emb @ w_ih_d^T + b_ih_d  [1001, 576]
    proj_kernel<<<dim3((CHAR_VOCAB + VB - 1) / VB, 2), G3>>>(emb, w_ih_f, b_ih_f, w_ih_b, b_ih_b);

    // 2) bidirectional GRU recurrence: 64 independent (batch, direction) CTAs
    gru_kernel<<<dim3(2, BATCH), H, SMEM_TOTAL>>>(char_ids, w_hh_f, b_hh_f, w_hh_b, b_hh_b);

    // 3) gather start/end hidden states into output [32, 512, 768]
    gather_kernel<<<dim3(NSPAN, BATCH), 192>>>(start_ids, end_ids, out);
}